// round 11
// baseline (speedup 1.0000x reference)
#include <cuda_runtime.h>
#include <cuda_fp16.h>
#include <mma.h>
#include <cstdint>

using namespace nvcuda;

#define NN 50000
#define EE 800000
#define DD 128
#define EPSI 0.001f
#define NCH 36                     // K = 2304 = 36 * 64 (18 per weight set)
#define MT 128                     // M tile rows per CTA
#define NTHR 256
#define LDAE 72                    // A tile ld (halfs), 144 B
#define LDBE 136                   // B tile ld (halfs), 272 B
#define LDCE 136                   // epilogue staging ld (halfs)
#define A_TILE (MT * LDAE * 2)     // 18432 B
#define B_TILE (64 * LDBE * 2)     // 17408 B
#define KAN_SMEM (2 * (A_TILE + B_TILE))  // 71680 B -> 3 CTAs/SM

// ---------------- device scratch ----------------------------------------------
__device__ float g_x[(size_t)NN * DD];
__device__ __half2 g_xh[(size_t)NN * 64];
__device__ __half2 g_aggh[2][(size_t)NN * 64];
__device__ float g_deg[NN];
__device__ __half g_wt[2 * 1152 * DD];  // [set][k][o]; k-order matches gen layout
__device__ int g_is64;

// ---------------- helpers ------------------------------------------------------
__device__ __forceinline__ uint32_t smem_u32(const void* p) {
    uint32_t a;
    asm("{ .reg .u64 t; cvta.to.shared.u64 t, %1; cvt.u32.u64 %0, t; }" : "=r"(a) : "l"(p));
    return a;
}
__device__ __forceinline__ void cp_async16(uint32_t dst, const void* src) {
    asm volatile("cp.async.cg.shared.global [%0], [%1], 16;" :: "r"(dst), "l"(src));
}
__device__ __forceinline__ void cp_commit() { asm volatile("cp.async.commit_group;"); }
__device__ __forceinline__ void cp_wait0() { asm volatile("cp.async.wait_group 0;"); }
__device__ __forceinline__ unsigned pack2h(float a, float b) {
    __half2 h = __floats2half2_rn(a, b);
    return *(unsigned*)&h;
}
__device__ __forceinline__ int get_idx(const void* p, long long e) {
    if (g_is64) return (int)((const long long*)p)[e];
    return ((const int*)p)[e];
}

// ---------------- local cubic B-spline: 4 nonzero bases -> 4 packed u32 -------
__device__ __forceinline__ void bs8_fast(float x, uint32_t* w) {
    float T = fmaf(x, 2.5f, 5.5f);
    T = fminf(fmaxf(T, 2.0f), 8.999f);
    float jf = floorf(T);
    float u = T - jf;
    int s = (int)jf - 3;
    float u2 = u * u, u3 = u2 * u;
    float v0 = fmaf(u, -0.5f, 1.0f / 6.0f);
    v0 = fmaf(u2, 0.5f, v0);
    v0 = fmaf(u3, -1.0f / 6.0f, v0);
    float v1 = fmaf(u2, -1.0f, 2.0f / 3.0f);
    v1 = fmaf(u3, 0.5f, v1);
    float v2 = fmaf(u, 0.5f, 1.0f / 6.0f);
    v2 = fmaf(u2, 0.5f, v2);
    v2 = fmaf(u3, -0.5f, v2);
    float v3 = u3 * (1.0f / 6.0f);
    uint32_t p01 = pack2h(v0, v1), p23 = pack2h(v2, v3);
    int sh = (s & 1) << 4;
    int p = s >> 1;
    uint32_t r0 = p01 << sh;
    uint32_t r1 = __funnelshift_l(p01, p23, sh);
    uint32_t r2 = sh ? (p23 >> 16) : 0u;
#pragma unroll
    for (int i = 0; i < 4; i++) {
        int d = i - p;
        w[i] = (d == 0) ? r0 : (d == 1) ? r1 : (d == 2) ? r2 : 0u;
    }
}

// ---------------- setup: x->half, clear agg/deg, weights->half, detect ---------
// Weight k-order (per set, 18 chunks of 64):
//   silu chunk c in {0,1}, col t: q=t>>5, dim = q*64 + c*32 + (t&31)
//   spline chunk cs=c-2, col t: q=t>>5, u=t&31, dim = q*64 + cs*4 + (u>>3), basis u&7
#define N_XH ((long long)NN * 32)
#define N_CLR ((long long)2 * NN * 16)
#define N_W ((long long)2 * 1152 * 128)
#define N_SETUP (N_XH + N_CLR + N_W + NN + 1)

__global__ void setup_kernel(const float* __restrict__ x,
                             const float* __restrict__ bwl, const float* __restrict__ swl,
                             const float* __restrict__ bwc, const float* __restrict__ swc,
                             const int* __restrict__ ei) {
    long long idx = (long long)blockIdx.x * 256 + threadIdx.x;
    if (idx < N_XH) {
        float4 v = ((const float4*)x)[idx];
        __half2 h0 = __floats2half2_rn(v.x, v.y);
        __half2 h1 = __floats2half2_rn(v.z, v.w);
        ((uint2*)g_xh)[idx] = make_uint2(*(uint32_t*)&h0, *(uint32_t*)&h1);
    } else if (idx < N_XH + N_CLR) {
        ((uint4*)g_aggh)[idx - N_XH] = make_uint4(0, 0, 0, 0);
    } else if (idx < N_XH + N_CLR + N_W) {
        long long r = idx - N_XH - N_CLR;
        int set = (int)(r / (1152 * 128));
        int rem = (int)(r - (long long)set * (1152 * 128));
        int kk = rem >> 7, o = rem & 127;
        int c = kk >> 6, t = kk & 63;
        const float* bw = set ? bwc : bwl;
        const float* sw = set ? swc : swl;
        float v;
        int q = t >> 5;
        if (c < 2) {
            int dim = q * 64 + c * 32 + (t & 31);
            v = bw[o * 128 + dim];
        } else {
            int cs = c - 2, u = t & 31;
            int dim = q * 64 + cs * 4 + (u >> 3);
            int b = u & 7;
            v = sw[(long long)o * 1024 + dim * 8 + b];
        }
        g_wt[r] = __float2half(v);
    } else if (idx < N_XH + N_CLR + N_W + NN) {
        g_deg[idx - N_XH - N_CLR - N_W] = 0.0f;
    } else if (idx == N_XH + N_CLR + N_W + NN) {
        int is64 = 1;
        for (int k = 0; k < 16; k++)
            if (ei[2 * k + 1] != 0) { is64 = 0; break; }
        g_is64 = is64;
    }
}

__global__ void deg_kernel(const void* __restrict__ ei) {
    int e = blockIdx.x * blockDim.x + threadIdx.x;
    if (e < EE) atomicAdd(&g_deg[get_idx(ei, (long long)EE + e)], 1.0f);
}

// ---------------- fused dual-branch KAN kernel (MT=128, 256 thr, 3 CTA/SM) -----
// out = xin + EPSI * ( featL(xh)@WL + featC(agg)@WC )
// 8 warps in 4m x 2n grid (warp tile 32x64). Each thread owns a 64-dim
// (128 B) sub-row of its feature row; all its silu+spline reads stay inside it.
template <int WH>
__global__ __launch_bounds__(NTHR, 3) void kan_fused(const __half2* __restrict__ hh,
                                                     const __half2* __restrict__ agg,
                                                     const float* __restrict__ xin,
                                                     float* __restrict__ out,
                                                     __half2* __restrict__ outh) {
    extern __shared__ char sm[];
    uint32_t smb = smem_u32(sm);
    int tid = threadIdx.x;
    int row0 = blockIdx.x * MT;

    int m = tid >> 1, q = tid & 1;             // 128 rows x 2 half-row threads
    bool valid = (row0 + m) < NN;
    int rowc = min(row0 + m, NN - 1);          // clamp: loads always in-bounds
    const __half2* hrow = hh + (size_t)rowc * 64;
    const __half2* arow = agg + (size_t)rowc * 64;

    const uint32_t aoff[2] = {0u, (uint32_t)A_TILE};
    uint32_t fbase = (uint32_t)(m * (LDAE * 2) + q * 64);

    uint32_t fr[16];                           // 32 halfs = this thread's k-slice
    const __half2 H2_ONE = __floats2half2_rn(1.0f, 1.0f);
    const __half2 H2_NL2E = __floats2half2_rn(-1.4426950408889634f, -1.4426950408889634f);

    auto gen = [&](int c) {                    // c compile-time after unroll
        const __half2* r = (c < 18) ? hrow : arow;
        int cs = (c < 18) ? c : c - 18;
        if (cs < 2) {                          // silu chunk: 32 values, pure half2
#pragma unroll
            for (int g = 0; g < 4; g++) {
                uint4 u = *(const uint4*)(r + q * 32 + cs * 16 + g * 4);
                uint32_t uw[4] = {u.x, u.y, u.z, u.w};
#pragma unroll
                for (int i = 0; i < 4; i++) {
                    __half2 h = *(__half2*)&uw[i];
                    __half2 e = h2exp2(__hmul2(h, H2_NL2E));       // exp(-h)
                    __half2 s = __hmul2(h, h2rcp(__hadd2(H2_ONE, e)));
                    fr[g * 4 + i] = *(uint32_t*)&s;
                }
            }
        } else {                               // spline chunk: 4 dims x 8 bases
            int csp = cs - 2;
            uint2 u2 = *(const uint2*)(r + q * 32 + csp * 2);
            float2 f0 = __half22float2(*(__half2*)&u2.x);
            float2 f1 = __half22float2(*(__half2*)&u2.y);
            bs8_fast(f0.x, fr);
            bs8_fast(f0.y, fr + 4);
            bs8_fast(f1.x, fr + 8);
            bs8_fast(f1.y, fr + 12);
        }
    };
    auto sts = [&](int buf) {
        uint32_t base = smb + aoff[buf] + fbase;
#pragma unroll
        for (int g = 0; g < 4; g++)
            asm volatile("st.shared.v4.b32 [%0], {%1,%2,%3,%4};"
                         :: "r"(base + g * 16), "r"(fr[g * 4 + 0]), "r"(fr[g * 4 + 1]),
                            "r"(fr[g * 4 + 2]), "r"(fr[g * 4 + 3]));
    };
    auto ldb = [&](int buf, int c) {
        const char* src = (const char*)(g_wt) + (size_t)c * 64 * DD * 2;
        uint32_t bb = smb + (uint32_t)(2 * A_TILE + buf * B_TILE);
#pragma unroll
        for (int qq = 0; qq < 4; qq++) {
            int i = tid + qq * NTHR;
            int r = i >> 4, c16 = i & 15;
            cp_async16(bb + r * (LDBE * 2) + c16 * 16, src + i * 16);
        }
        cp_commit();
    };

    int warp = tid >> 5;
    int m0 = (warp & 3) * 32, n0 = (warp >> 2) * 64;   // 4m x 2n, warp tile 32x64
    wmma::fragment<wmma::accumulator, 16, 16, 16, __half> acc[2][4];
#pragma unroll
    for (int i = 0; i < 2; i++)
#pragma unroll
        for (int j = 0; j < 4; j++) wmma::fill_fragment(acc[i][j], __float2half(0.0f));

    // prologue
    gen(0); sts(0); ldb(0, 0);

#pragma unroll
    for (int c = 0; c < NCH; c++) {            // FULL unroll: c compile-time
        const int cb = c & 1, nb = cb ^ 1;
        if (c + 1 < NCH) gen(c + 1);
        cp_wait0();
        __syncthreads();
        if (c + 1 < NCH) { sts(nb); ldb(nb, c + 1); }

        const __half* As = (const __half*)(sm + aoff[cb]);
        const __half* Bs = (const __half*)(sm + 2 * A_TILE + cb * B_TILE);
#pragma unroll
        for (int kk = 0; kk < 4; kk++) {
            wmma::fragment<wmma::matrix_a, 16, 16, 16, __half, wmma::row_major> a0, a1;
            wmma::load_matrix_sync(a0, As + m0 * LDAE + kk * 16, LDAE);
            wmma::load_matrix_sync(a1, As + (m0 + 16) * LDAE + kk * 16, LDAE);
#pragma unroll
            for (int j = 0; j < 4; j++) {
                wmma::fragment<wmma::matrix_b, 16, 16, 16, __half, wmma::row_major> bf;
                wmma::load_matrix_sync(bf, Bs + kk * 16 * LDBE + n0 + j * 16, LDBE);
                wmma::mma_sync(acc[0][j], a0, bf, acc[0][j]);
                wmma::mma_sync(acc[1][j], a1, bf, acc[1][j]);
            }
        }
    }

    // epilogue: stage half tile (128 x LDCE), fused Euler update + half mirror
    __syncthreads();
    __half* cs = (__half*)sm;
#pragma unroll
    for (int i = 0; i < 2; i++)
#pragma unroll
        for (int j = 0; j < 4; j++)
            wmma::store_matrix_sync(cs + (m0 + i * 16) * LDCE + n0 + j * 16, acc[i][j],
                                    LDCE, wmma::mem_row_major);
    __syncthreads();

    if (valid) {
        const __half2* crow = (const __half2*)(cs + m * LDCE + q * 64);
        float4* po = (float4*)(out + (size_t)(row0 + m) * DD + q * 64);
        const float4* xr = (const float4*)(xin + (size_t)(row0 + m) * DD + q * 64);
        uint2* ph = (uint2*)(outh + (size_t)(row0 + m) * 64 + q * 32);
#pragma unroll
        for (int g = 0; g < 16; g++) {
            float2 a0 = __half22float2(crow[g * 2]);
            float2 a1 = __half22float2(crow[g * 2 + 1]);
            float4 x4 = xr[g];
            float4 o = make_float4(x4.x + EPSI * a0.x, x4.y + EPSI * a0.y,
                                   x4.z + EPSI * a1.x, x4.w + EPSI * a1.y);
            po[g] = o;
            if (WH) {
                __half2 h0 = __floats2half2_rn(o.x, o.y);
                __half2 h1 = __floats2half2_rn(o.z, o.w);
                ph[g] = make_uint2(*(uint32_t*)&h0, *(uint32_t*)&h1);
            }
        }
    }
}

// ---------------- half scatter: agg[dst] += rsqrt(ds+1)rsqrt(dd+1) * h[src] ----
__global__ void scatter_half(const uint4* __restrict__ hh, const void* __restrict__ ei,
                             __half2* __restrict__ agg) {
    long long gid = (long long)blockIdx.x * blockDim.x + threadIdx.x;
    long long e = gid >> 4;
    int lane = (int)(gid & 15);
    if (e >= EE) return;
    int src = get_idx(ei, e);
    int dst = get_idx(ei, (long long)EE + e);
    float nrm = rsqrtf(g_deg[src] + 1.0f) * rsqrtf(g_deg[dst] + 1.0f);
    __half2 nh = __float2half2_rn(nrm);
    uint4 v = hh[(size_t)src * 16 + lane];
    __half2 a0 = __hmul2(*(__half2*)&v.x, nh);
    __half2 a1 = __hmul2(*(__half2*)&v.y, nh);
    __half2 a2 = __hmul2(*(__half2*)&v.z, nh);
    __half2 a3 = __hmul2(*(__half2*)&v.w, nh);
    __half2* p = agg + (size_t)dst * 64 + lane * 4;
    asm volatile("red.global.add.noftz.v4.f16x2 [%0], {%1,%2,%3,%4};"
                 :: "l"(p), "r"(*(uint32_t*)&a0), "r"(*(uint32_t*)&a1),
                    "r"(*(uint32_t*)&a2), "r"(*(uint32_t*)&a3) : "memory");
}

// ---------------- launch -------------------------------------------------------
extern "C" void kernel_launch(void* const* d_in, const int* in_sizes, int n_in,
                              void* d_out, int out_size) {
    const float* x = (const float*)d_in[0];
    const void* ei = d_in[1];
    const float* bwl = (const float*)d_in[2];
    const float* swl = (const float*)d_in[3];
    const float* bwc = (const float*)d_in[4];
    const float* swc = (const float*)d_in[5];
    float* out = (float*)d_out;

    cudaFuncSetAttribute(kan_fused<0>, cudaFuncAttributeMaxDynamicSharedMemorySize, KAN_SMEM);
    cudaFuncSetAttribute(kan_fused<1>, cudaFuncAttributeMaxDynamicSharedMemorySize, KAN_SMEM);

    void *xp, *xhp, *aggp;
    cudaGetSymbolAddress(&xp, g_x);
    cudaGetSymbolAddress(&xhp, g_xh);
    cudaGetSymbolAddress(&aggp, g_aggh);
    float* gx = (float*)xp;
    __half2* gxh = (__half2*)xhp;
    __half2* agg0 = (__half2*)aggp;
    __half2* agg1 = agg0 + (size_t)NN * 64;

    const int GRID_KAN = (NN + MT - 1) / MT;   // 391 -> single wave at 3 CTA/SM

    // launches: 1 setup  2 deg  3 scatter0  4 kan0 (ncu capture)  5 scatter1  6 kan1
    setup_kernel<<<(int)((N_SETUP + 255) / 256), 256>>>(x, bwl, swl, bwc, swc, (const int*)ei);
    deg_kernel<<<(EE + 255) / 256, 256>>>(ei);

    scatter_half<<<(int)((EE * 16LL + 255) / 256), 256>>>((const uint4*)gxh, ei, agg0);
    kan_fused<1><<<GRID_KAN, NTHR, KAN_SMEM>>>(gxh, agg0, x, gx, gxh);

    scatter_half<<<(int)((EE * 16LL + 255) / 256), 256>>>((const uint4*)gxh, ei, agg1);
    kan_fused<0><<<GRID_KAN, NTHR, KAN_SMEM>>>(gxh, agg1, gx, out, gxh);
}

// round 12
// speedup vs baseline: 1.1341x; 1.1341x over previous
#include <cuda_runtime.h>
#include <cuda_fp16.h>
#include <mma.h>
#include <cstdint>

using namespace nvcuda;

#define NN 50000
#define EE 800000
#define DD 128
#define EPSI 0.001f
#define NCH 36                     // K = 2304 = 36 * 64 (18 per weight set)
#define MT 128                     // M tile rows per CTA
#define NTHR 512
#define LDAE 72                    // A tile ld (halfs), 144 B
#define LDBE 136                   // B tile ld (halfs), 272 B
#define LDCE 136                   // epilogue staging ld (halfs)
#define A_TILE (MT * LDAE * 2)     // 18432 B
#define B_TILE (64 * LDBE * 2)     // 17408 B
#define KAN_SMEM (2 * (A_TILE + B_TILE))  // 71680 B

// ---------------- device scratch ----------------------------------------------
__device__ float g_x[(size_t)NN * DD];
__device__ __half2 g_xh[(size_t)NN * 64];
__device__ __half2 g_aggh[2][(size_t)NN * 64];
__device__ float g_deg[NN];
__device__ __half g_wt[2 * 1152 * DD];  // [set][k][o], k-major (36 chunks of 64 k)
__device__ int g_is64;

// ---------------- helpers ------------------------------------------------------
__device__ __forceinline__ uint32_t smem_u32(const void* p) {
    uint32_t a;
    asm("{ .reg .u64 t; cvta.to.shared.u64 t, %1; cvt.u32.u64 %0, t; }" : "=r"(a) : "l"(p));
    return a;
}
__device__ __forceinline__ void cp_async16(uint32_t dst, const void* src) {
    asm volatile("cp.async.cg.shared.global [%0], [%1], 16;" :: "r"(dst), "l"(src));
}
__device__ __forceinline__ void cp_commit() { asm volatile("cp.async.commit_group;"); }
__device__ __forceinline__ void cp_wait0() { asm volatile("cp.async.wait_group 0;"); }
__device__ __forceinline__ unsigned pack2h(float a, float b) {
    __half2 h = __floats2half2_rn(a, b);
    return *(unsigned*)&h;
}
__device__ __forceinline__ int get_idx(const void* p, long long e) {
    if (g_is64) return (int)((const long long*)p)[e];
    return ((const int*)p)[e];
}

// ---------------- local cubic B-spline: 4 nonzero bases -> 4 packed u32 -------
__device__ __forceinline__ void bs8_fast(float x, uint32_t* w) {
    float T = fmaf(x, 2.5f, 5.5f);
    T = fminf(fmaxf(T, 2.0f), 8.999f);
    float jf = floorf(T);
    float u = T - jf;
    int s = (int)jf - 3;
    float u2 = u * u, u3 = u2 * u;
    float v0 = fmaf(u, -0.5f, 1.0f / 6.0f);
    v0 = fmaf(u2, 0.5f, v0);
    v0 = fmaf(u3, -1.0f / 6.0f, v0);
    float v1 = fmaf(u2, -1.0f, 2.0f / 3.0f);
    v1 = fmaf(u3, 0.5f, v1);
    float v2 = fmaf(u, 0.5f, 1.0f / 6.0f);
    v2 = fmaf(u2, 0.5f, v2);
    v2 = fmaf(u3, -0.5f, v2);
    float v3 = u3 * (1.0f / 6.0f);
    uint32_t p01 = pack2h(v0, v1), p23 = pack2h(v2, v3);
    int sh = (s & 1) << 4;
    int p = s >> 1;
    uint32_t r0 = p01 << sh;
    uint32_t r1 = __funnelshift_l(p01, p23, sh);
    uint32_t r2 = sh ? (p23 >> 16) : 0u;
#pragma unroll
    for (int i = 0; i < 4; i++) {
        int d = i - p;
        w[i] = (d == 0) ? r0 : (d == 1) ? r1 : (d == 2) ? r2 : 0u;
    }
}

// ---------------- setup: x->half, clear agg, weights->half, detect, degree -----
// g_deg must be zeroed (memsetAsync) BEFORE this kernel: the degree range here
// does atomics into it, and intra-kernel block order is undefined.
#define N_XH ((long long)NN * 32)
#define N_CLR ((long long)2 * NN * 16)
#define N_W ((long long)2 * 1152 * 128)
#define N_SETUP (N_XH + N_CLR + N_W + 1 + EE)

__global__ void setup_kernel(const float* __restrict__ x,
                             const float* __restrict__ bwl, const float* __restrict__ swl,
                             const float* __restrict__ bwc, const float* __restrict__ swc,
                             const int* __restrict__ ei) {
    long long idx = (long long)blockIdx.x * 256 + threadIdx.x;
    if (idx < N_XH) {
        float4 v = ((const float4*)x)[idx];
        __half2 h0 = __floats2half2_rn(v.x, v.y);
        __half2 h1 = __floats2half2_rn(v.z, v.w);
        ((uint2*)g_xh)[idx] = make_uint2(*(uint32_t*)&h0, *(uint32_t*)&h1);
    } else if (idx < N_XH + N_CLR) {
        ((uint4*)g_aggh)[idx - N_XH] = make_uint4(0, 0, 0, 0);
    } else if (idx < N_XH + N_CLR + N_W) {
        long long r = idx - N_XH - N_CLR;
        int set = (int)(r / (1152 * 128));
        int q = (int)(r - (long long)set * (1152 * 128));
        int k = q >> 7, o = q & 127;
        const float* bw = set ? bwc : bwl;
        const float* sw = set ? swc : swl;
        float v = (k < DD) ? bw[o * DD + k] : sw[(long long)o * 1024 + (k - DD)];
        g_wt[r] = __float2half(v);
    } else if (idx == N_XH + N_CLR + N_W) {
        int is64 = 1;
        for (int k = 0; k < 16; k++)
            if (ei[2 * k + 1] != 0) { is64 = 0; break; }
        g_is64 = is64;
    } else if (idx < N_SETUP) {
        long long e = idx - (N_XH + N_CLR + N_W + 1);
        // local dtype detect (same deterministic first-16-pairs test)
        int is64 = 1;
#pragma unroll
        for (int k = 0; k < 16; k++)
            if (ei[2 * k + 1] != 0) { is64 = 0; break; }
        int dst = is64 ? (int)((const long long*)ei)[(long long)EE + e]
                       : ei[(long long)EE + e];
        atomicAdd(&g_deg[dst], 1.0f);
    }
}

// ---------------- fused dual-branch KAN kernel (MT=128, 512 thr, fp16 acc) -----
// out = xin + EPSI * ( featL(xh)@WL + featC(agg)@WC )
// Fully-unrolled chunk loop; double-buffered A/B with cp.async on B.
template <int WH>
__global__ __launch_bounds__(NTHR, 2) void kan_fused(const __half2* __restrict__ hh,
                                                     const __half2* __restrict__ agg,
                                                     const float* __restrict__ xin,
                                                     float* __restrict__ out,
                                                     __half2* __restrict__ outh) {
    extern __shared__ char sm[];
    uint32_t smb = smem_u32(sm);
    int tid = threadIdx.x;
    int row0 = blockIdx.x * MT;

    int m = tid >> 2, q = tid & 3;             // 128 rows x 4 quarter-threads
    bool valid = (row0 + m) < NN;
    int rowc = min(row0 + m, NN - 1);          // clamp: loads always in-bounds
    const __half2* hrow = hh + (size_t)rowc * 64;
    const __half2* arow = agg + (size_t)rowc * 64;

    const uint32_t aoff[2] = {0u, (uint32_t)A_TILE};
    const uint32_t boff[2] = {(uint32_t)(2 * A_TILE), (uint32_t)(2 * A_TILE + B_TILE)};
    uint32_t fbase = (uint32_t)(m * (LDAE * 2) + q * 32);

    uint32_t fr[8];                            // 16 half = this thread's k-slice
    const __half2 H2_ONE = __floats2half2_rn(1.0f, 1.0f);
    const __half2 H2_NL2E = __floats2half2_rn(-1.4426950408889634f, -1.4426950408889634f);

    auto gen = [&](int c) {                    // c compile-time after unroll
        const __half2* r = (c < 18) ? hrow : arow;
        int cs = (c < 18) ? c : c - 18;
        if (cs < 2) {                          // silu chunk: 16 values, pure half2
#pragma unroll
            for (int g = 0; g < 2; g++) {
                uint4 u = *(const uint4*)(r + cs * 32 + q * 8 + g * 4);
                uint32_t uw[4] = {u.x, u.y, u.z, u.w};
#pragma unroll
                for (int i = 0; i < 4; i++) {
                    __half2 h = *(__half2*)&uw[i];
                    __half2 e = h2exp2(__hmul2(h, H2_NL2E));       // exp(-h)
                    __half2 s = __hmul2(h, h2rcp(__hadd2(H2_ONE, e)));
                    fr[g * 4 + i] = *(uint32_t*)&s;
                }
            }
        } else {                               // spline chunk: 2 dims x 8 bases
            float2 f = __half22float2(r[(cs - 2) * 4 + q]);
            bs8_fast(f.x, fr);
            bs8_fast(f.y, fr + 4);
        }
    };
    auto sts = [&](int buf) {
        uint32_t base = smb + aoff[buf] + fbase;
        asm volatile("st.shared.v4.b32 [%0], {%1,%2,%3,%4};"
                     :: "r"(base), "r"(fr[0]), "r"(fr[1]), "r"(fr[2]), "r"(fr[3]));
        asm volatile("st.shared.v4.b32 [%0], {%1,%2,%3,%4};"
                     :: "r"(base + 16), "r"(fr[4]), "r"(fr[5]), "r"(fr[6]), "r"(fr[7]));
    };
    auto ldb = [&](int buf, int c) {
        const char* src = (const char*)(g_wt) + (size_t)c * 64 * DD * 2;
#pragma unroll
        for (int qq = 0; qq < 2; qq++) {
            int i = tid + qq * NTHR;
            int r = i >> 4, c16 = i & 15;
            cp_async16(smb + boff[buf] + r * (LDBE * 2) + c16 * 16, src + i * 16);
        }
        cp_commit();
    };

    int warp = tid >> 5;
    int m0 = (warp & 3) * 32, n0 = (warp >> 2) * 32;   // 4x4 warp grid, 32x32 tiles
    wmma::fragment<wmma::accumulator, 16, 16, 16, __half> acc[2][2];
#pragma unroll
    for (int i = 0; i < 2; i++)
#pragma unroll
        for (int j = 0; j < 2; j++) wmma::fill_fragment(acc[i][j], __float2half(0.0f));

    gen(0); sts(0); ldb(0, 0);

#pragma unroll
    for (int c = 0; c < NCH; c++) {            // FULL unroll: c compile-time
        const int cb = c & 1, nb = cb ^ 1;
        if (c + 1 < NCH) gen(c + 1);
        cp_wait0();
        __syncthreads();
        if (c + 1 < NCH) { sts(nb); ldb(nb, c + 1); }

        const __half* As = (const __half*)(sm + aoff[cb]);
        const __half* Bs = (const __half*)(sm + boff[cb]);
#pragma unroll
        for (int kk = 0; kk < 4; kk++) {
            wmma::fragment<wmma::matrix_a, 16, 16, 16, __half, wmma::row_major> a0, a1;
            wmma::load_matrix_sync(a0, As + m0 * LDAE + kk * 16, LDAE);
            wmma::load_matrix_sync(a1, As + (m0 + 16) * LDAE + kk * 16, LDAE);
#pragma unroll
            for (int j = 0; j < 2; j++) {
                wmma::fragment<wmma::matrix_b, 16, 16, 16, __half, wmma::row_major> bf;
                wmma::load_matrix_sync(bf, Bs + kk * 16 * LDBE + n0 + j * 16, LDBE);
                wmma::mma_sync(acc[0][j], a0, bf, acc[0][j]);
                wmma::mma_sync(acc[1][j], a1, bf, acc[1][j]);
            }
        }
    }

    // epilogue: stage half tile (128 x LDCE), fused Euler update + half mirror
    __syncthreads();
    __half* cs = (__half*)sm;
#pragma unroll
    for (int i = 0; i < 2; i++)
#pragma unroll
        for (int j = 0; j < 2; j++)
            wmma::store_matrix_sync(cs + (m0 + i * 16) * LDCE + n0 + j * 16, acc[i][j],
                                    LDCE, wmma::mem_row_major);
    __syncthreads();

    if (valid) {
        const __half2* crow = (const __half2*)(cs + m * LDCE + q * 32);
        float4* po = (float4*)(out + (size_t)(row0 + m) * DD + q * 32);
        const float4* xr = (const float4*)(xin + (size_t)(row0 + m) * DD + q * 32);
        uint2* ph = (uint2*)(outh + (size_t)(row0 + m) * 64 + q * 16);
#pragma unroll
        for (int g = 0; g < 8; g++) {
            float2 a0 = __half22float2(crow[g * 2]);
            float2 a1 = __half22float2(crow[g * 2 + 1]);
            float4 x4 = xr[g];
            float4 o = make_float4(x4.x + EPSI * a0.x, x4.y + EPSI * a0.y,
                                   x4.z + EPSI * a1.x, x4.w + EPSI * a1.y);
            po[g] = o;
            if (WH) {
                __half2 h0 = __floats2half2_rn(o.x, o.y);
                __half2 h1 = __floats2half2_rn(o.z, o.w);
                ph[g] = make_uint2(*(uint32_t*)&h0, *(uint32_t*)&h1);
            }
        }
    }
}

// ---------------- half scatter: agg[dst] += rsqrt(ds+1)rsqrt(dd+1) * h[src] ----
__global__ void scatter_half(const uint4* __restrict__ hh, const void* __restrict__ ei,
                             __half2* __restrict__ agg) {
    long long gid = (long long)blockIdx.x * blockDim.x + threadIdx.x;
    long long e = gid >> 4;
    int lane = (int)(gid & 15);
    if (e >= EE) return;
    int src = get_idx(ei, e);
    int dst = get_idx(ei, (long long)EE + e);
    float nrm = rsqrtf(g_deg[src] + 1.0f) * rsqrtf(g_deg[dst] + 1.0f);
    __half2 nh = __float2half2_rn(nrm);
    uint4 v = hh[(size_t)src * 16 + lane];
    __half2 a0 = __hmul2(*(__half2*)&v.x, nh);
    __half2 a1 = __hmul2(*(__half2*)&v.y, nh);
    __half2 a2 = __hmul2(*(__half2*)&v.z, nh);
    __half2 a3 = __hmul2(*(__half2*)&v.w, nh);
    __half2* p = agg + (size_t)dst * 64 + lane * 4;
    asm volatile("red.global.add.noftz.v4.f16x2 [%0], {%1,%2,%3,%4};"
                 :: "l"(p), "r"(*(uint32_t*)&a0), "r"(*(uint32_t*)&a1),
                    "r"(*(uint32_t*)&a2), "r"(*(uint32_t*)&a3) : "memory");
}

// ---------------- launch -------------------------------------------------------
extern "C" void kernel_launch(void* const* d_in, const int* in_sizes, int n_in,
                              void* d_out, int out_size) {
    const float* x = (const float*)d_in[0];
    const void* ei = d_in[1];
    const float* bwl = (const float*)d_in[2];
    const float* swl = (const float*)d_in[3];
    const float* bwc = (const float*)d_in[4];
    const float* swc = (const float*)d_in[5];
    float* out = (float*)d_out;

    cudaFuncSetAttribute(kan_fused<0>, cudaFuncAttributeMaxDynamicSharedMemorySize, KAN_SMEM);
    cudaFuncSetAttribute(kan_fused<1>, cudaFuncAttributeMaxDynamicSharedMemorySize, KAN_SMEM);

    void *xp, *xhp, *aggp, *degp;
    cudaGetSymbolAddress(&xp, g_x);
    cudaGetSymbolAddress(&xhp, g_xh);
    cudaGetSymbolAddress(&aggp, g_aggh);
    cudaGetSymbolAddress(&degp, g_deg);
    float* gx = (float*)xp;
    __half2* gxh = (__half2*)xhp;
    __half2* agg0 = (__half2*)aggp;
    __half2* agg1 = agg0 + (size_t)NN * 64;

    const int GRID_KAN = (NN + MT - 1) / MT;   // 391

    // launches: 1 memset(deg)  2 setup(+degree)  3 scatter0  4 kan0 (ncu)  5 scatter1  6 kan1
    cudaMemsetAsync(degp, 0, NN * sizeof(float));
    setup_kernel<<<(int)((N_SETUP + 255) / 256), 256>>>(x, bwl, swl, bwc, swc, (const int*)ei);

    scatter_half<<<(int)((EE * 16LL + 255) / 256), 256>>>((const uint4*)gxh, ei, agg0);
    kan_fused<1><<<GRID_KAN, NTHR, KAN_SMEM>>>(gxh, agg0, x, gx, gxh);

    scatter_half<<<(int)((EE * 16LL + 255) / 256), 256>>>((const uint4*)gxh, ei, agg1);
    kan_fused<0><<<GRID_KAN, NTHR, KAN_SMEM>>>(gxh, agg1, gx, out, gxh);
}